// round 4
// baseline (speedup 1.0000x reference)
#include <cuda_runtime.h>
#include <cuda_bf16.h>

#define Bq 32
#define Nq 325
#define Kq 20
#define S_IN 12
#define S_OUTq 12
#define Cq 10
#define Hq 48            // 4*S_OUT
#define BNq (Bq*Nq)      // 10400

__device__ float g_wh[BNq*S_OUTq];
__device__ float g_hx[BNq*Hq];
__device__ float g_hy[BNq*Hq];
__device__ float g_wT[Cq*Hq];                   // a2_W transposed (contiguous)
__device__ double g_acc[3] = {0.0, 0.0, 0.0};   // wh_sum, dist_sum, cl_sum
__device__ int g_counter = 0;

__device__ __forceinline__ float leaky(float x){ return x >= 0.f ? x : 0.5f*x; }

// ---------------- k1: warp per (b,n) row ----------------
__global__ __launch_bounds__(256) void k1(
        const float* __restrict__ inp, const float* __restrict__ wW,
        const float* __restrict__ wb,  const float* __restrict__ a1W,
        const float* __restrict__ a2W){
    int t = threadIdx.x;
    int warp = t >> 5, lane = t & 31;
    int bn = blockIdx.x * 8 + warp;

    if (blockIdx.x == 0) {   // transpose a2_W once
        for (int i = t; i < Cq*Hq; i += 256) {
            int c = i / Hq, d = i % Hq;
            g_wT[c*Hq + d] = a2W[d*Cq + c];
        }
    }

    float whsum = 0.f;
    if (bn < BNq) {
        float xin = (lane < S_IN) ? inp[bn*S_IN + lane] : 0.f;
        float wh = (lane < S_OUTq) ? wb[lane] : 0.f;
        #pragma unroll
        for (int i = 0; i < S_IN; i++) {
            float xi = __shfl_sync(0xffffffffu, xin, i);
            if (lane < S_OUTq) wh += xi * wW[i*S_OUTq + lane];
        }
        wh = leaky(wh);
        if (lane < S_OUTq) { g_wh[bn*S_OUTq + lane] = wh; whsum = wh; }

        int d2 = 32 + (lane & 15);
        float ax = 0.f, ay = 0.f, ax2 = 0.f, ay2 = 0.f;
        #pragma unroll
        for (int s = 0; s < S_OUTq; s++) {
            float w = __shfl_sync(0xffffffffu, wh, s);
            ax  += w * a1W[s*Hq + lane];
            ay  += w * a1W[(S_OUTq+s)*Hq + lane];
            ax2 += w * a1W[s*Hq + d2];
            ay2 += w * a1W[(S_OUTq+s)*Hq + d2];
        }
        g_hx[bn*Hq + lane] = ax;
        g_hy[bn*Hq + lane] = ay;
        if (lane < 16) { g_hx[bn*Hq + d2] = ax2; g_hy[bn*Hq + d2] = ay2; }
    }
    #pragma unroll
    for (int o = 16; o; o >>= 1) whsum += __shfl_down_sync(0xffffffffu, whsum, o);
    __shared__ float sred[8];
    if (lane == 0) sred[warp] = whsum;
    __syncthreads();
    if (t == 0) {
        float s = 0.f;
        #pragma unroll
        for (int w = 0; w < 8; w++) s += sred[w];
        atomicAdd(&g_acc[0], (double)s);
    }
}

// ---------------- k2: block per (b,n), 128 thr, warp-specialized ----------------
__global__ __launch_bounds__(128) void k2(
        const float* __restrict__ a1b, const float* __restrict__ a2b,
        const int* __restrict__ idx, float* __restrict__ out, int out_size){
    int bn = blockIdx.x;
    int b  = bn / Nq;
    int t  = threadIdx.x;
    int warp = t >> 5, lane = t & 31;

    __shared__ int   s_j[Kq];
    __shared__ __align__(16) float s_hxb[Hq];       // hx + a1_b
    __shared__ __align__(16) float s_wT[Cq][Hq];    // broadcast-only reads
    __shared__ __align__(16) float s_att[Kq][12];   // softmaxed, [10..11]=0
    __shared__ __align__(16) float s_wht[Kq][12];
    __shared__ float s_inv[Kq];
    __shared__ float s_a2b[Cq];

    // ---- phase A: stage everything (no internal sync; idx reloaded where needed)
    if (t < Kq) s_j[t] = idx[bn*Kq + t];
    if (t < Cq) s_a2b[t] = a2b[t];
    if (t >= 16 && t < 28) {
        int q = t - 16;
        float4 hx = ((const float4*)(g_hx + bn*Hq))[q];
        float4 bb = ((const float4*)a1b)[q];
        ((float4*)s_hxb)[q] = make_float4(hx.x+bb.x, hx.y+bb.y, hx.z+bb.z, hx.w+bb.w);
    }
    if (t < 120) ((float4*)s_wT)[t] = ((const float4*)g_wT)[t];
    {
        int u = t - 64;            // threads 64..123 gather wh_topk (60 float4)
        if (u >= 0 && u < Kq*3) {
            int k = u / 3, q = u % 3;
            int j = idx[bn*Kq + k];
            ((float4*)s_wht[k])[q] = ((const float4*)(g_wh + (b*Nq + j)*S_OUTq))[q];
        }
    }
    __syncthreads();

    float myatt[Cq];               // warp 0, lane<20: softmaxed attention row
    float4 mw0, mw1, mw2;          // own wht row
    float myinv = 0.f;

    if (warp == 0 && lane < Kq) {
        // ---- phase C: attention row k=lane, acc in regs, hy straight from global
        const float4* hy = (const float4*)(g_hy + (size_t)(b*Nq + s_j[lane])*Hq);
        float acc[Cq];
        #pragma unroll
        for (int c = 0; c < Cq; c++) acc[c] = s_a2b[c];
        #pragma unroll 4
        for (int q = 0; q < 12; q++) {
            float4 h = hy[q];
            float4 x = ((const float4*)s_hxb)[q];
            h.x = leaky(h.x + x.x); h.y = leaky(h.y + x.y);
            h.z = leaky(h.z + x.z); h.w = leaky(h.w + x.w);
            #pragma unroll
            for (int c = 0; c < Cq; c++) {
                float4 w = ((const float4*)s_wT[c])[q];   // warp broadcast
                acc[c] += h.x*w.x + h.y*w.y + h.z*w.z + h.w*w.w;
            }
        }
        // leaky + softmax fully in registers
        float m = -1e30f;
        #pragma unroll
        for (int c = 0; c < Cq; c++) { acc[c] = leaky(acc[c]); m = fmaxf(m, acc[c]); }
        float sum = 0.f;
        #pragma unroll
        for (int c = 0; c < Cq; c++) { acc[c] = __expf(acc[c] - m); sum += acc[c]; }
        float inv = __fdividef(1.f, sum);
        #pragma unroll
        for (int c = 0; c < Cq; c++) { acc[c] *= inv; myatt[c] = acc[c]; s_att[lane][c] = acc[c]; }
        s_att[lane][10] = 0.f; s_att[lane][11] = 0.f;
    } else if (warp == 1 && lane < Kq) {
        // ---- norms
        float4 w0 = ((const float4*)s_wht[lane])[0];
        float4 w1 = ((const float4*)s_wht[lane])[1];
        float4 w2 = ((const float4*)s_wht[lane])[2];
        float ss = w0.x*w0.x + w0.y*w0.y + w0.z*w0.z + w0.w*w0.w
                 + w1.x*w1.x + w1.y*w1.y + w1.z*w1.z + w1.w*w1.w
                 + w2.x*w2.x + w2.y*w2.y + w2.z*w2.z + w2.w*w2.w;
        s_inv[lane] = __fdividef(1.f, sqrtf(ss) + 1e-8f);
    }
    __syncthreads();

    if (warp == 0) {
        // ---- pairs: full 20x20 via broadcasts; own rows stay in registers
        float dsum = 0.f, csum = 0.f;
        if (lane < Kq) {
            mw0 = ((const float4*)s_wht[lane])[0];
            mw1 = ((const float4*)s_wht[lane])[1];
            mw2 = ((const float4*)s_wht[lane])[2];
            myinv = s_inv[lane];
            #pragma unroll 4
            for (int l = 0; l < Kq; l++) {
                float4 u0 = ((const float4*)s_wht[l])[0];   // broadcasts
                float4 u1 = ((const float4*)s_wht[l])[1];
                float4 u2 = ((const float4*)s_wht[l])[2];
                float d = mw0.x*u0.x + mw0.y*u0.y + mw0.z*u0.z + mw0.w*u0.w
                        + mw1.x*u1.x + mw1.y*u1.y + mw1.z*u1.z + mw1.w*u1.w
                        + mw2.x*u2.x + mw2.y*u2.y + mw2.z*u2.z + mw2.w*u2.w;
                d *= myinv * s_inv[l];
                dsum += d;
                if (l != lane) {
                    float4 p0 = ((const float4*)s_att[l])[0];
                    float4 p1 = ((const float4*)s_att[l])[1];
                    float4 p2 = ((const float4*)s_att[l])[2];
                    float pr = myatt[0]*p0.x + myatt[1]*p0.y + myatt[2]*p0.z + myatt[3]*p0.w
                             + myatt[4]*p1.x + myatt[5]*p1.y + myatt[6]*p1.z + myatt[7]*p1.w
                             + myatt[8]*p2.x + myatt[9]*p2.y;
                    pr = fminf(fmaxf(pr, 1e-4f), 1.f - 1e-4f);
                    float lp = __logf(pr);
                    csum += (d >= 0.5f) ? -lp : lp;
                }
            }
        }
        #pragma unroll
        for (int o = 16; o; o >>= 1) {
            dsum += __shfl_down_sync(0xffffffffu, dsum, o);
            csum += __shfl_down_sync(0xffffffffu, csum, o);
        }
        if (lane == 0) {
            atomicAdd(&g_acc[1], (double)dsum);
            atomicAdd(&g_acc[2], (double)csum);
            __threadfence();
            int done = atomicAdd(&g_counter, 1);
            if (done == BNq - 1) {
                out[out_size - 3] = (float)(g_acc[2] / (double)BNq);
                out[out_size - 2] = (float)(g_acc[1] / (double)((long long)BNq*Kq*Kq));
                out[out_size - 1] = (float)(g_acc[0] / (double)((long long)BNq*S_OUTq));
                g_acc[0] = 0.0; g_acc[1] = 0.0; g_acc[2] = 0.0;
                g_counter = 0;
            }
        }
    } else if (warp == 1 && lane < 30) {
        // ---- einsum: 30 float4 outputs, per-k reads are broadcast-friendly
        int c = lane / 3, q = lane % 3;
        float4 o = make_float4(0.f, 0.f, 0.f, 0.f);
        #pragma unroll
        for (int k = 0; k < Kq; k++) {
            float a = s_att[k][c];                    // 10 distinct words
            float4 w = ((const float4*)s_wht[k])[q];  // 3 distinct float4
            o.x += a*w.x; o.y += a*w.y; o.z += a*w.z; o.w += a*w.w;
        }
        ((float4*)(out + bn*Cq*S_OUTq))[lane] = o;
    }
}

extern "C" void kernel_launch(void* const* d_in, const int* in_sizes, int n_in,
                              void* d_out, int out_size) {
    const float* input_data = (const float*)d_in[1];
    const float* wW  = (const float*)d_in[2];
    const float* wb  = (const float*)d_in[3];
    const float* a1W = (const float*)d_in[4];
    const float* a1b = (const float*)d_in[5];
    const float* a2W = (const float*)d_in[6];
    const float* a2b = (const float*)d_in[7];
    const int*   idx = (const int*)d_in[8];
    float* out = (float*)d_out;

    k1<<<(BNq + 7) / 8, 256>>>(input_data, wW, wb, a1W, a2W);
    k2<<<BNq, 128>>>(a1b, a2b, idx, out, out_size);
}

// round 5
// speedup vs baseline: 1.0822x; 1.0822x over previous
#include <cuda_runtime.h>
#include <cuda_bf16.h>

#define Bq 32
#define Nq 325
#define Kq 20
#define S_IN 12
#define S_OUTq 12
#define Cq 10
#define Hq 48            // 4*S_OUT
#define BNq (Bq*Nq)      // 10400

__device__ float g_wh[BNq*S_OUTq];
__device__ float g_hx[BNq*Hq];
__device__ float g_hy[BNq*Hq];
__device__ float g_wT[Cq*Hq];                   // a2_W transposed (contiguous)
__device__ double g_acc[3] = {0.0, 0.0, 0.0};   // wh_sum, dist_sum, cl_sum
__device__ int g_counter = 0;

__device__ __forceinline__ float leaky(float x){ return x >= 0.f ? x : 0.5f*x; }

// ---------------- k1: warp per (b,n) row ----------------
__global__ __launch_bounds__(256) void k1(
        const float* __restrict__ inp, const float* __restrict__ wW,
        const float* __restrict__ wb,  const float* __restrict__ a1W,
        const float* __restrict__ a2W){
    int t = threadIdx.x;
    int warp = t >> 5, lane = t & 31;
    int bn = blockIdx.x * 8 + warp;

    if (blockIdx.x == 0) {   // transpose a2_W once
        for (int i = t; i < Cq*Hq; i += 256) {
            int c = i / Hq, d = i % Hq;
            g_wT[c*Hq + d] = a2W[d*Cq + c];
        }
    }

    float whsum = 0.f;
    if (bn < BNq) {
        float xin = (lane < S_IN) ? inp[bn*S_IN + lane] : 0.f;
        float wh = (lane < S_OUTq) ? wb[lane] : 0.f;
        #pragma unroll
        for (int i = 0; i < S_IN; i++) {
            float xi = __shfl_sync(0xffffffffu, xin, i);
            if (lane < S_OUTq) wh += xi * wW[i*S_OUTq + lane];
        }
        wh = leaky(wh);
        if (lane < S_OUTq) { g_wh[bn*S_OUTq + lane] = wh; whsum = wh; }

        int d2 = 32 + (lane & 15);
        float ax = 0.f, ay = 0.f, ax2 = 0.f, ay2 = 0.f;
        #pragma unroll
        for (int s = 0; s < S_OUTq; s++) {
            float w = __shfl_sync(0xffffffffu, wh, s);
            ax  += w * a1W[s*Hq + lane];
            ay  += w * a1W[(S_OUTq+s)*Hq + lane];
            ax2 += w * a1W[s*Hq + d2];
            ay2 += w * a1W[(S_OUTq+s)*Hq + d2];
        }
        g_hx[bn*Hq + lane] = ax;
        g_hy[bn*Hq + lane] = ay;
        if (lane < 16) { g_hx[bn*Hq + d2] = ax2; g_hy[bn*Hq + d2] = ay2; }
    }
    #pragma unroll
    for (int o = 16; o; o >>= 1) whsum += __shfl_down_sync(0xffffffffu, whsum, o);
    __shared__ float sred[8];
    if (lane == 0) sred[warp] = whsum;
    __syncthreads();
    if (t == 0) {
        float s = 0.f;
        #pragma unroll
        for (int w = 0; w < 8; w++) s += sred[w];
        atomicAdd(&g_acc[0], (double)s);
    }
}

// ---------------- k2: warp per (b,n), 4 warps/block ----------------
__global__ __launch_bounds__(128) void k2(
        const float* __restrict__ a1b, const float* __restrict__ a2b,
        const int* __restrict__ idx, float* __restrict__ out, int out_size){
    int t = threadIdx.x;
    int warp = t >> 5, lane = t & 31;
    int bn = blockIdx.x * 4 + warp;
    int b  = bn / Nq;

    __shared__ __align__(16) float s_wT[Cq*Hq];      // block-shared, broadcast reads
    __shared__ __align__(16) float s_hxb[4][Hq];     // per-warp: hx + a1_b
    __shared__ __align__(16) float s_att[4][Kq][12];
    __shared__ __align__(16) float s_wht[4][Kq][12];
    __shared__ float s_inv[4][Kq];

    // stage wT cooperatively (only cross-warp dependency)
    for (int i = t; i < 120; i += 128)
        ((float4*)s_wT)[i] = ((const float4*)g_wT)[i];

    // per-warp staging: hxb, wht rows (+norms, kept in regs too)
    if (lane < 12) {
        float4 hx = ((const float4*)(g_hx + bn*Hq))[lane];
        float4 bb = ((const float4*)a1b)[lane];
        ((float4*)s_hxb[warp])[lane] =
            make_float4(hx.x+bb.x, hx.y+bb.y, hx.z+bb.z, hx.w+bb.w);
    }
    int j = 0;
    float4 mw0, mw1, mw2;
    float myinv = 0.f;
    if (lane < Kq) {
        j = idx[bn*Kq + lane];
        const float4* w = (const float4*)(g_wh + (size_t)(b*Nq + j)*S_OUTq);
        mw0 = w[0]; mw1 = w[1]; mw2 = w[2];
        ((float4*)s_wht[warp][lane])[0] = mw0;
        ((float4*)s_wht[warp][lane])[1] = mw1;
        ((float4*)s_wht[warp][lane])[2] = mw2;
        float ss = mw0.x*mw0.x + mw0.y*mw0.y + mw0.z*mw0.z + mw0.w*mw0.w
                 + mw1.x*mw1.x + mw1.y*mw1.y + mw1.z*mw1.z + mw1.w*mw1.w
                 + mw2.x*mw2.x + mw2.y*mw2.y + mw2.z*mw2.z + mw2.w*mw2.w;
        myinv = __fdividef(1.f, sqrtf(ss) + 1e-8f);
        s_inv[warp][lane] = myinv;
    }
    __syncthreads();

    // attention row k=lane: accumulators in regs, hy straight from global,
    // wT/hxb consumed as pure warp broadcasts. Softmax entirely in registers.
    float myatt[Cq];
    if (lane < Kq) {
        const float4* hy = (const float4*)(g_hy + (size_t)(b*Nq + j)*Hq);
        float acc[Cq];
        #pragma unroll
        for (int c = 0; c < Cq; c++) acc[c] = __ldg(&a2b[c]);
        #pragma unroll 4
        for (int q = 0; q < 12; q++) {
            float4 h = hy[q];
            float4 x = ((const float4*)s_hxb[warp])[q];
            h.x = leaky(h.x + x.x); h.y = leaky(h.y + x.y);
            h.z = leaky(h.z + x.z); h.w = leaky(h.w + x.w);
            #pragma unroll
            for (int c = 0; c < Cq; c++) {
                float4 w = ((const float4*)(s_wT + c*Hq))[q];   // broadcast
                acc[c] += h.x*w.x + h.y*w.y + h.z*w.z + h.w*w.w;
            }
        }
        float m = -1e30f;
        #pragma unroll
        for (int c = 0; c < Cq; c++) { acc[c] = leaky(acc[c]); m = fmaxf(m, acc[c]); }
        float sum = 0.f;
        #pragma unroll
        for (int c = 0; c < Cq; c++) { acc[c] = __expf(acc[c] - m); sum += acc[c]; }
        float inv = __fdividef(1.f, sum);
        #pragma unroll
        for (int c = 0; c < Cq; c++) { acc[c] *= inv; myatt[c] = acc[c]; }
        ((float4*)s_att[warp][lane])[0] = make_float4(acc[0], acc[1], acc[2], acc[3]);
        ((float4*)s_att[warp][lane])[1] = make_float4(acc[4], acc[5], acc[6], acc[7]);
        ((float4*)s_att[warp][lane])[2] = make_float4(acc[8], acc[9], 0.f, 0.f);
    }
    __syncwarp();

    // pairs: full 20x20 via broadcasts; own rows stay in registers
    float dsum = 0.f, csum = 0.f;
    if (lane < Kq) {
        #pragma unroll 4
        for (int l = 0; l < Kq; l++) {
            float4 u0 = ((const float4*)s_wht[warp][l])[0];
            float4 u1 = ((const float4*)s_wht[warp][l])[1];
            float4 u2 = ((const float4*)s_wht[warp][l])[2];
            float d = mw0.x*u0.x + mw0.y*u0.y + mw0.z*u0.z + mw0.w*u0.w
                    + mw1.x*u1.x + mw1.y*u1.y + mw1.z*u1.z + mw1.w*u1.w
                    + mw2.x*u2.x + mw2.y*u2.y + mw2.z*u2.z + mw2.w*u2.w;
            d *= myinv * s_inv[warp][l];
            dsum += d;
            if (l != lane) {
                float4 p0 = ((const float4*)s_att[warp][l])[0];
                float4 p1 = ((const float4*)s_att[warp][l])[1];
                float4 p2 = ((const float4*)s_att[warp][l])[2];
                float pr = myatt[0]*p0.x + myatt[1]*p0.y + myatt[2]*p0.z + myatt[3]*p0.w
                         + myatt[4]*p1.x + myatt[5]*p1.y + myatt[6]*p1.z + myatt[7]*p1.w
                         + myatt[8]*p2.x + myatt[9]*p2.y;
                pr = fminf(fmaxf(pr, 1e-4f), 1.f - 1e-4f);
                float lp = __logf(pr);
                csum += (d >= 0.5f) ? -lp : lp;
            }
        }
    }
    #pragma unroll
    for (int o = 16; o; o >>= 1) {
        dsum += __shfl_down_sync(0xffffffffu, dsum, o);
        csum += __shfl_down_sync(0xffffffffu, csum, o);
    }
    if (lane == 0) {
        atomicAdd(&g_acc[1], (double)dsum);
        atomicAdd(&g_acc[2], (double)csum);
        __threadfence();
        int done = atomicAdd(&g_counter, 1);
        if (done == BNq - 1) {   // last warp finalizes + resets for next replay
            out[out_size - 3] = (float)(g_acc[2] / (double)BNq);
            out[out_size - 2] = (float)(g_acc[1] / (double)((long long)BNq*Kq*Kq));
            out[out_size - 1] = (float)(g_acc[0] / (double)((long long)BNq*S_OUTq));
            g_acc[0] = 0.0; g_acc[1] = 0.0; g_acc[2] = 0.0;
            g_counter = 0;
        }
    }

    // einsum: 30 lanes, 30 float4 outputs; broadcast-friendly reads
    if (lane < 30) {
        int c = lane / 3, q = lane % 3;
        float4 o = make_float4(0.f, 0.f, 0.f, 0.f);
        #pragma unroll
        for (int k = 0; k < Kq; k++) {
            float a = s_att[warp][k][c];                    // 10 consecutive words
            float4 w = ((const float4*)s_wht[warp][k])[q];  // 3 consecutive float4
            o.x += a*w.x; o.y += a*w.y; o.z += a*w.z; o.w += a*w.w;
        }
        ((float4*)(out + (size_t)bn*Cq*S_OUTq))[lane] = o;
    }
}

extern "C" void kernel_launch(void* const* d_in, const int* in_sizes, int n_in,
                              void* d_out, int out_size) {
    const float* input_data = (const float*)d_in[1];
    const float* wW  = (const float*)d_in[2];
    const float* wb  = (const float*)d_in[3];
    const float* a1W = (const float*)d_in[4];
    const float* a1b = (const float*)d_in[5];
    const float* a2W = (const float*)d_in[6];
    const float* a2b = (const float*)d_in[7];
    const int*   idx = (const int*)d_in[8];
    float* out = (float*)d_out;

    k1<<<(BNq + 7) / 8, 256>>>(input_data, wW, wb, a1W, a2W);
    k2<<<BNq / 4, 128>>>(a1b, a2b, idx, out, out_size);
}